// round 1
// baseline (speedup 1.0000x reference)
#include <cuda_runtime.h>

// MultiStageFIRFilter: y = x + sum_{a=1..20} xa_a,
//   xa_a[b,t] = (1/a) * sum_{k=0..24} mc[b,t,k] * xa_{a-1}[b,t-k]  (xa_0 = x, causal zero-pad)
//
// Single fused kernel, halo-recompute across the 20 sequential stages.

#define NB      4
#define NT      16384
#define M       25        // taps
#define STAGES  20
#define HALO    480       // STAGES * (M-1)
#define THREADS 512
#define EXT     1024      // positions per block (2 per thread)
#define TILE    544       // EXT - HALO
#define PAD     24        // zero left-pad in smem
#define NTILES  31        // ceil(16384 / 544)

__global__ __launch_bounds__(THREADS, 1)
void fir_kernel(const float* __restrict__ x, const float* __restrict__ mc,
                float* __restrict__ out)
{
    __shared__ __align__(16) float s0[PAD + EXT];
    __shared__ __align__(16) float s1[PAD + EXT];

    const int tile = blockIdx.x % NTILES;
    const int b    = blockIdx.x / NTILES;
    const int t0   = tile * TILE;
    const int tid  = threadIdx.x;
    const int i0   = 2 * tid;              // local position index (even)
    const int p0   = t0 - HALO + i0;       // global time of first owned position

    if (tid < PAD) { s0[tid] = 0.0f; s1[tid] = 0.0f; }

    // ---- load per-position coefficients into registers (2 rows x 25) ----
    float cc[50];
    const size_t rowbase = (size_t)b * NT;
    if (p0 >= 0 && p0 + 1 < NT) {
        // rows p0 and p0+1 are 50 contiguous floats, 8B-aligned (p0 even)
        const float2* g = (const float2*)(mc + (rowbase + (size_t)p0) * M);
        #pragma unroll
        for (int k = 0; k < 25; k++) {
            float2 v = g[k];
            cc[2*k] = v.x; cc[2*k+1] = v.y;
        }
    } else {
        #pragma unroll
        for (int r = 0; r < 2; r++) {
            int p = p0 + r;
            if (p >= 0 && p < NT) {
                const float* g = mc + (rowbase + (size_t)p) * M;
                #pragma unroll
                for (int k = 0; k < M; k++) cc[25*r + k] = g[k];
            } else {
                #pragma unroll
                for (int k = 0; k < M; k++) cc[25*r + k] = 0.0f;
            }
        }
    }

    // ---- stage 0: xa = x ----
    float xv0 = (p0     >= 0 && p0     < NT) ? x[rowbase + p0]     : 0.0f;
    float xv1 = (p0 + 1 >= 0 && p0 + 1 < NT) ? x[rowbase + p0 + 1] : 0.0f;
    float y0 = xv0, y1 = xv1;

    ((float2*)(s0 + PAD))[tid] = make_float2(xv0, xv1);
    __syncthreads();

    float* cur = s0;
    float* nxt = s1;
    const bool ghost = (p0 < 0);   // positions before t=0: xa stays exactly 0

    #pragma unroll
    for (int a = 1; a <= STAGES; a++) {
        const float inv = 1.0f / (float)a;   // folds to a constant (loop unrolled)

        // window w[j] = xa[p0 - 24 + j], j = 0..25  (conflict-free LDS.64)
        float w[26];
        const float2* wp = (const float2*)(cur + i0);
        #pragma unroll
        for (int j = 0; j < 13; j++) {
            float2 v = wp[j];
            w[2*j] = v.x; w[2*j+1] = v.y;
        }

        float acc0 = 0.0f, acc1 = 0.0f;
        #pragma unroll
        for (int j = 0; j < 25; j++) {
            acc0 = fmaf(cc[24 - j],      w[j],     acc0);   // out p0:   k = 24-j
            acc1 = fmaf(cc[25 + 24 - j], w[j + 1], acc1);   // out p0+1
        }
        acc0 *= inv; acc1 *= inv;
        if (ghost) { acc0 = 0.0f; acc1 = 0.0f; }
        y0 += acc0; y1 += acc1;

        ((float2*)(nxt + PAD))[tid] = make_float2(acc0, acc1);
        __syncthreads();
        float* tmp = cur; cur = nxt; nxt = tmp;
    }

    // ---- write the owned (non-halo) outputs ----
    if (i0 >= HALO) {
        if (p0     < NT) out[rowbase + p0]     = y0;
        if (p0 + 1 < NT) out[rowbase + p0 + 1] = y1;
    }
}

extern "C" void kernel_launch(void* const* d_in, const int* in_sizes, int n_in,
                              void* d_out, int out_size)
{
    const float* x  = (const float*)d_in[0];   // (4, 16384) float32
    const float* mc = (const float*)d_in[1];   // (4, 16384, 25) float32
    float* out = (float*)d_out;                // (4, 16384) float32
    fir_kernel<<<NB * NTILES, THREADS>>>(x, mc, out);
}